// round 9
// baseline (speedup 1.0000x reference)
#include <cuda_runtime.h>
#include <cstdint>

// ===================== scratch (device globals; no allocation allowed) ======
#define MAXN 20000
#define MAXE 400000
__device__ float g_H[(size_t)MAXN * 1280];    // GEMM out (fp32, dis[row]-scaled)
__device__ float g_X[(size_t)MAXN * 1280];    // GEMM input (tf32-rounded fp32)
__device__ float g_A[(size_t)MAXN * 320];     // layer-3 gather out (fp32)
__device__ float g_WT1[1280 * 1280];
__device__ float g_WT2[640 * 1280];
__device__ float g_WT3[320 * 640];
__device__ float g_dis[MAXN];
__device__ int   g_deg[MAXN];
__device__ int   g_rowptr[MAXN + 1];
__device__ int   g_cursor[MAXN];
__device__ int   g_col[MAXE];
__device__ float g_pool[64 * 320];
__device__ float g_m1[64 * 1024];
__device__ float g_mc[64 * 193];
__device__ float g_m3[64 * 1024];
__device__ float g_m4[64 * 512];

// ===================== helpers =====================
__device__ __forceinline__ uint32_t f2tf32(float x) {
    uint32_t r;
    asm("cvt.rna.tf32.f32 %0, %1;" : "=r"(r) : "f"(x));
    return r;
}
__device__ __forceinline__ void mma_tf32(float* d, const uint32_t* a, const uint32_t* b) {
    asm volatile(
        "mma.sync.aligned.m16n8k8.row.col.f32.tf32.tf32.f32 "
        "{%0,%1,%2,%3}, {%4,%5,%6,%7}, {%8,%9}, {%0,%1,%2,%3};\n"
        : "+f"(d[0]), "+f"(d[1]), "+f"(d[2]), "+f"(d[3])
        : "r"(a[0]), "r"(a[1]), "r"(a[2]), "r"(a[3]), "r"(b[0]), "r"(b[1]));
}
__device__ __forceinline__ uint32_t smem_u32(const void* p) {
    uint32_t a;
    asm("{ .reg .u64 t; cvta.to.shared.u64 t, %1; cvt.u32.u64 %0, t; }" : "=r"(a) : "l"(p));
    return a;
}

// ===================== degree / normalization =====================
__global__ void k_init_deg(int* deg, int n) {
    int i = blockIdx.x * blockDim.x + threadIdx.x;
    if (i < n) deg[i] = 1;
}
__global__ void k_count_deg(const int* __restrict__ dst, int* deg, int e) {
    int i = blockIdx.x * blockDim.x + threadIdx.x;
    if (i < e) atomicAdd(&deg[dst[i]], 1);
}
__global__ void k_dis(const int* __restrict__ deg, float* dis, int n) {
    int i = blockIdx.x * blockDim.x + threadIdx.x;
    if (i < n) dis[i] = rsqrtf((float)deg[i]);
}

// ===================== CSR build =====================
// single-block scan, warp-shuffle based; deg cached in regs between passes
#define SCHUNK 20
__global__ void __launch_bounds__(1024)
k_scan(const int* __restrict__ deg, int* __restrict__ rowptr,
       int* __restrict__ cursor, int n) {
    __shared__ int warpsum[32];
    const int tid = threadIdx.x;
    const int lane = tid & 31, wid = tid >> 5;
    const int chunk = (n + 1023) / 1024;   // <= SCHUNK for n <= 20480
    const int start = tid * chunk;
    const int end = (start + chunk < n) ? start + chunk : n;
    int dcache[SCHUNK];
    int s = 0;
    for (int i = start; i < end; i++) { dcache[i - start] = deg[i]; s += dcache[i - start]; }
    int v = s;
#pragma unroll
    for (int o = 1; o < 32; o <<= 1) {
        int u = __shfl_up_sync(0xFFFFFFFFu, v, o);
        if (lane >= o) v += u;
    }
    if (lane == 31) warpsum[wid] = v;
    __syncthreads();
    if (wid == 0) {
        int w = warpsum[lane];
#pragma unroll
        for (int o = 1; o < 32; o <<= 1) {
            int u = __shfl_up_sync(0xFFFFFFFFu, w, o);
            if (lane >= o) w += u;
        }
        warpsum[lane] = w;
    }
    __syncthreads();
    int incl = v + (wid ? warpsum[wid - 1] : 0);
    int run = incl - s;                 // exclusive prefix
    for (int i = start; i < end; i++) {
        rowptr[i] = run;
        cursor[i] = run;
        run += dcache[i - start];
    }
    if (start < n && end == n) rowptr[n] = run;
}

__global__ void k_fill_edges(const int* __restrict__ src, const int* __restrict__ dst,
                             int* cursor, int* __restrict__ col, int e) {
    int i = blockIdx.x * blockDim.x + threadIdx.x;
    if (i < e) {
        int pos = atomicAdd(&cursor[dst[i]], 1);
        col[pos] = src[i];
    }
}
__global__ void k_fill_self(int* cursor, int* __restrict__ col, int n) {
    int i = blockIdx.x * blockDim.x + threadIdx.x;
    if (i < n) {
        int pos = atomicAdd(&cursor[i], 1);
        col[pos] = i;
    }
}

// ===================== conversions =====================
__global__ void k_f2tf(const float* __restrict__ in, float* __restrict__ out, size_t n4) {
    size_t i = (size_t)blockIdx.x * blockDim.x + threadIdx.x;
    if (i < n4) {
        float4 v = *(const float4*)(in + i * 4);
        float4 o;
        o.x = __uint_as_float(f2tf32(v.x));
        o.y = __uint_as_float(f2tf32(v.y));
        o.z = __uint_as_float(f2tf32(v.z));
        o.w = __uint_as_float(f2tf32(v.w));
        *(float4*)(out + i * 4) = o;
    }
}

__global__ void k_wt(const float* __restrict__ W, float* __restrict__ WT,
                     int K, int M) {
    __shared__ float t[32][33];
    int k0 = blockIdx.y * 32, m0 = blockIdx.x * 32;
    int tx = threadIdx.x, ty = threadIdx.y;   // 32 x 8
#pragma unroll
    for (int i = ty; i < 32; i += 8)
        t[i][tx] = W[(size_t)(k0 + i) * M + m0 + tx];
    __syncthreads();
#pragma unroll
    for (int i = ty; i < 32; i += 8)
        WT[(size_t)(m0 + i) * K + k0 + tx] = __uint_as_float(f2tf32(t[tx][i]));
}

// ===================== tf32 tensor-core GEMM (cp.async, 4-stage) ============
// C[N, M] = (Atf[N, K] @ WT[M, K]^T) * dis[row]    (C fp32)
// Block tile 128x256, BK=16, 256 threads (8 warps 2x4), warp tile 64x64.
// SMEM rows: 20 words (16 data + 4 pad) -> conflict-free fragment loads.
// Stage = A(10KB) + B(20KB) = 30KB; 4 stages = 120KB dynamic SMEM, 1 CTA/SM.
#define GW 20
#define AW (128 * GW)
#define BW (256 * GW)
#define STAGE_WORDS (AW + BW)
#define NSTAGE 4

__global__ void __launch_bounds__(256, 1)
k_gemm_tf(const float* __restrict__ Atf, const float* __restrict__ WT,
          float* __restrict__ C, const float* __restrict__ dis,
          int N, int K, int M) {
    extern __shared__ uint32_t smem[];
    const uint32_t sbase0 = smem_u32(smem);
    const int tid = threadIdx.x;
    const int wid = tid >> 5;
    const int lid = tid & 31;
    const int g4  = lid >> 2;
    const int tg  = lid & 3;
    const int wm  = wid >> 2;     // 0..1
    const int wn  = wid & 3;      // 0..3
    const int row0 = blockIdx.y * 128;
    const int col0 = blockIdx.x * 256;
    const int nk = K >> 4;

    float acc[4][8][4];
#pragma unroll
    for (int i = 0; i < 4; i++)
#pragma unroll
        for (int j = 0; j < 8; j++)
#pragma unroll
            for (int k = 0; k < 4; k++) acc[i][j][k] = 0.0f;

    auto load_stage = [&](int s, int kt) {
        const int k0 = kt << 4;
        const uint32_t sb = sbase0 + (uint32_t)s * STAGE_WORDS * 4;
        // A: 128 rows x 16 floats = 512 float4; 2 per thread
#pragma unroll
        for (int i = 0; i < 2; i++) {
            int c = tid + i * 256;
            int row = c >> 2, off = c & 3;
            int gr = row0 + row;
            int grc = gr < N ? gr : N - 1;
            const float* src = Atf + (size_t)grc * K + k0 + off * 4;
            uint32_t dst = sb + (uint32_t)(row * GW + off * 4) * 4;
            int sz = (gr < N) ? 16 : 0;
            asm volatile("cp.async.cg.shared.global [%0], [%1], 16, %2;"
                         :: "r"(dst), "l"(src), "r"(sz));
        }
        // B: 256 n-rows x 16 floats = 1024 float4; 4 per thread
#pragma unroll
        for (int i = 0; i < 4; i++) {
            int c = tid + i * 256;
            int n = c >> 2, off = c & 3;
            int gc = col0 + n;
            int gcc = gc < M ? gc : M - 1;
            const float* src = WT + (size_t)gcc * K + k0 + off * 4;
            uint32_t dst = sb + (uint32_t)(AW + n * GW + off * 4) * 4;
            int sz = (gc < M) ? 16 : 0;
            asm volatile("cp.async.cg.shared.global [%0], [%1], 16, %2;"
                         :: "r"(dst), "l"(src), "r"(sz));
        }
        asm volatile("cp.async.commit_group;" ::: "memory");
    };

    for (int s = 0; s < NSTAGE - 1 && s < nk; s++) load_stage(s, s);

    for (int t = 0; t < nk; t++) {
        if (t + NSTAGE - 1 <= nk)
            asm volatile("cp.async.wait_group %0;" :: "n"(NSTAGE - 2) : "memory");
        else
            asm volatile("cp.async.wait_group 0;" ::: "memory");
        __syncthreads();
        if (t + NSTAGE - 1 < nk) load_stage((t + NSTAGE - 1) % NSTAGE, t + NSTAGE - 1);

        const uint32_t* as = smem + ((t % NSTAGE) * STAGE_WORDS);
        const uint32_t* bs = as + AW;
#pragma unroll
        for (int s = 0; s < 2; s++) {
            const int kw = s * 8;
            uint32_t af[4][4], bf[8][2];
#pragma unroll
            for (int mi = 0; mi < 4; mi++) {
                int r = wm * 64 + mi * 16 + g4;
                af[mi][0] = as[r * GW + kw + tg];
                af[mi][1] = as[(r + 8) * GW + kw + tg];
                af[mi][2] = as[r * GW + kw + tg + 4];
                af[mi][3] = as[(r + 8) * GW + kw + tg + 4];
            }
#pragma unroll
            for (int nf = 0; nf < 8; nf++) {
                int cc = wn * 64 + nf * 8 + g4;
                bf[nf][0] = bs[cc * GW + kw + tg];
                bf[nf][1] = bs[cc * GW + kw + tg + 4];
            }
#pragma unroll
            for (int mi = 0; mi < 4; mi++)
#pragma unroll
                for (int nf = 0; nf < 8; nf++)
                    mma_tf32(acc[mi][nf], af[mi], bf[nf]);
        }
    }

#pragma unroll
    for (int mi = 0; mi < 4; mi++) {
        int r0 = row0 + wm * 64 + mi * 16 + g4;
        float d0 = (r0 < N) ? dis[r0] : 0.f;
        float d1 = (r0 + 8 < N) ? dis[r0 + 8] : 0.f;
#pragma unroll
        for (int nf = 0; nf < 8; nf++) {
            int cc = col0 + wn * 64 + nf * 8 + tg * 2;
            if (cc < M) {
                if (r0 < N)
                    *(float2*)(C + (size_t)r0 * M + cc) =
                        make_float2(acc[mi][nf][0] * d0, acc[mi][nf][1] * d0);
                if (r0 + 8 < N)
                    *(float2*)(C + (size_t)(r0 + 8) * M + cc) =
                        make_float2(acc[mi][nf][2] * d1, acc[mi][nf][3] * d1);
            }
        }
    }
}

// ===================== CSR gather (float4, edge-unrolled) ====================
__global__ void k_gather4(const float* __restrict__ H, float* __restrict__ out,
                          const int* __restrict__ rowptr, const int* __restrict__ col,
                          const float* __restrict__ dis, const float* __restrict__ b,
                          int M, int fo, int tfround) {
    const int d = blockIdx.x;
    const int t = threadIdx.x;
    float4 acc = make_float4(0.f, 0.f, 0.f, 0.f);
    const int beg = rowptr[d];
    const int end = rowptr[d + 1];
    int j = beg;
    for (; j + 1 < end; j += 2) {
        const int s0 = __ldg(&col[j]);
        const int s1 = __ldg(&col[j + 1]);
        float4 v0 = __ldg((const float4*)(H + (size_t)s0 * M + fo) + t);
        float4 v1 = __ldg((const float4*)(H + (size_t)s1 * M + fo) + t);
        acc.x += v0.x + v1.x;
        acc.y += v0.y + v1.y;
        acc.z += v0.z + v1.z;
        acc.w += v0.w + v1.w;
    }
    if (j < end) {
        const int s0 = __ldg(&col[j]);
        float4 v0 = __ldg((const float4*)(H + (size_t)s0 * M + fo) + t);
        acc.x += v0.x; acc.y += v0.y; acc.z += v0.z; acc.w += v0.w;
    }
    const float wd = dis[d];
    float4 bb = __ldg((const float4*)(b + fo) + t);
    float4 r;
    r.x = fmaxf(acc.x * wd + bb.x, 0.f);
    r.y = fmaxf(acc.y * wd + bb.y, 0.f);
    r.z = fmaxf(acc.z * wd + bb.z, 0.f);
    r.w = fmaxf(acc.w * wd + bb.w, 0.f);
    if (tfround) {
        r.x = __uint_as_float(f2tf32(r.x));
        r.y = __uint_as_float(f2tf32(r.y));
        r.z = __uint_as_float(f2tf32(r.z));
        r.w = __uint_as_float(f2tf32(r.w));
    }
    ((float4*)(out + (size_t)d * M + fo))[t] = r;
}

// ===================== per-graph mean pool (batch sorted) ===================
__global__ void k_pool2(const float* __restrict__ A, const int* __restrict__ batch,
                        float* __restrict__ pool, int N) {
    const int g = blockIdx.x;
    const int f = threadIdx.x;   // 320
    int lo = 0, hi = N;
    while (lo < hi) { int mid = (lo + hi) >> 1; if (batch[mid] < g) lo = mid + 1; else hi = mid; }
    const int beg = lo;
    hi = N;
    while (lo < hi) { int mid = (lo + hi) >> 1; if (batch[mid] < g + 1) lo = mid + 1; else hi = mid; }
    const int end = lo;
    float s = 0.f;
    for (int i = beg; i < end; i++) s += A[(size_t)i * 320 + f];
    pool[g * 320 + f] = s / fmaxf((float)(end - beg), 1.0f);
}

// ===================== MLP head =====================
__global__ void k_mlp(const float* __restrict__ in, const float* __restrict__ W,
                      const float* __restrict__ b, float* __restrict__ out,
                      int K, int M, int istride, int ostride, int ooff, int dorelu) {
    int g = blockIdx.y;
    int m = blockIdx.x * blockDim.x + threadIdx.x;
    if (m >= M) return;
    const float* ing = in + (size_t)g * istride;
    float acc = b[m];
    for (int k = 0; k < K; k++) acc += ing[k] * W[(size_t)k * M + m];
    if (dorelu) acc = fmaxf(acc, 0.0f);
    out[(size_t)g * ostride + ooff + m] = acc;
}

__global__ void k_copyfp(const float* __restrict__ fp, float* __restrict__ mc) {
    int idx = blockIdx.x * blockDim.x + threadIdx.x;
    if (idx < 64 * 65) {
        int g = idx / 65, j = idx % 65;
        mc[g * 193 + j] = fp[idx];
    }
}

__global__ void k_final(const float* __restrict__ in, const float* __restrict__ Wo,
                        const float* __restrict__ bo, float* __restrict__ out) {
    int g = blockIdx.x;
    float acc = 0.f;
    for (int k = threadIdx.x; k < 512; k += 32) acc += in[g * 512 + k] * Wo[k];
#pragma unroll
    for (int o = 16; o; o >>= 1) acc += __shfl_down_sync(0xFFFFFFFFu, acc, o);
    if (threadIdx.x == 0) out[g] = acc + bo[0];
}

// ===================== launch =====================
extern "C" void kernel_launch(void* const* d_in, const int* in_sizes, int n_in,
                              void* d_out, int out_size) {
    const float* x     = (const float*)d_in[0];
    const int*   ei    = (const int*)d_in[1];
    const int*   batch = (const int*)d_in[2];
    const float* fp_x  = (const float*)d_in[3];
    const float* W1 = (const float*)d_in[4];   const float* b1 = (const float*)d_in[5];
    const float* W2 = (const float*)d_in[6];   const float* b2 = (const float*)d_in[7];
    const float* W3 = (const float*)d_in[8];   const float* b3 = (const float*)d_in[9];
    const float* Wg1 = (const float*)d_in[10]; const float* bg1 = (const float*)d_in[11];
    const float* Wg2 = (const float*)d_in[12]; const float* bg2 = (const float*)d_in[13];
    const float* Wf1 = (const float*)d_in[14]; const float* bf1 = (const float*)d_in[15];
    const float* Wf2 = (const float*)d_in[16]; const float* bf2 = (const float*)d_in[17];
    const float* Wo  = (const float*)d_in[18]; const float* bo  = (const float*)d_in[19];

    const int N = in_sizes[0] / 1280;
    const int E = in_sizes[1] / 2;
    const int G = in_sizes[3] / 65;
    const int* srcp = ei;
    const int* dstp = ei + E;

    float *pH, *pX, *pA, *pdis, *ppool, *pm1, *pmc, *pm3, *pm4;
    float *pWT1, *pWT2, *pWT3;
    int *pdeg, *prowptr, *pcursor, *pcol;
    cudaGetSymbolAddress((void**)&pH, g_H);
    cudaGetSymbolAddress((void**)&pX, g_X);
    cudaGetSymbolAddress((void**)&pA, g_A);
    cudaGetSymbolAddress((void**)&pWT1, g_WT1);
    cudaGetSymbolAddress((void**)&pWT2, g_WT2);
    cudaGetSymbolAddress((void**)&pWT3, g_WT3);
    cudaGetSymbolAddress((void**)&pdis, g_dis);
    cudaGetSymbolAddress((void**)&pdeg, g_deg);
    cudaGetSymbolAddress((void**)&prowptr, g_rowptr);
    cudaGetSymbolAddress((void**)&pcursor, g_cursor);
    cudaGetSymbolAddress((void**)&pcol, g_col);
    cudaGetSymbolAddress((void**)&ppool, g_pool);
    cudaGetSymbolAddress((void**)&pm1, g_m1);
    cudaGetSymbolAddress((void**)&pmc, g_mc);
    cudaGetSymbolAddress((void**)&pm3, g_m3);
    cudaGetSymbolAddress((void**)&pm4, g_m4);

    cudaFuncSetAttribute(k_gemm_tf, cudaFuncAttributeMaxDynamicSharedMemorySize,
                         NSTAGE * STAGE_WORDS * 4);

    // degree / normalization / CSR
    k_init_deg<<<(N + 255) / 256, 256>>>(pdeg, N);
    k_count_deg<<<(E + 255) / 256, 256>>>(dstp, pdeg, E);
    k_dis<<<(N + 255) / 256, 256>>>(pdeg, pdis, N);
    k_scan<<<1, 1024>>>(pdeg, prowptr, pcursor, N);
    k_fill_edges<<<(E + 255) / 256, 256>>>(srcp, dstp, pcursor, pcol, E);
    k_fill_self<<<(N + 255) / 256, 256>>>(pcursor, pcol, N);

    // conversions: x -> tf32-rounded fp32, weights -> tf32 transposed
    {
        size_t n4 = (size_t)N * 1280 / 4;
        k_f2tf<<<(unsigned)((n4 + 255) / 256), 256>>>(x, pX, n4);
        dim3 bt(32, 8);
        k_wt<<<dim3(1280 / 32, 1280 / 32), bt>>>(W1, pWT1, 1280, 1280);
        k_wt<<<dim3(640 / 32, 1280 / 32), bt>>>(W2, pWT2, 1280, 640);
        k_wt<<<dim3(320 / 32, 640 / 32), bt>>>(W3, pWT3, 640, 320);
    }

    const unsigned smem_bytes = NSTAGE * STAGE_WORDS * 4;
    auto gemm = [&](const float* in, const float* WT, int K, int M) {
        dim3 gg((M + 255) / 256, (N + 127) / 128);
        k_gemm_tf<<<gg, 256, smem_bytes>>>(in, WT, pH, pdis, N, K, M);
    };

    // layer 1 (gather in two 640-feature passes to keep H-half L2-resident)
    gemm(pX, pWT1, 1280, 1280);
    k_gather4<<<N, 160>>>(pH, pX, prowptr, pcol, pdis, b1, 1280, 0,   1);
    k_gather4<<<N, 160>>>(pH, pX, prowptr, pcol, pdis, b1, 1280, 640, 1);
    // layer 2
    gemm(pX, pWT2, 1280, 640);
    k_gather4<<<N, 160>>>(pH, pX, prowptr, pcol, pdis, b2, 640, 0, 1);
    // layer 3
    gemm(pX, pWT3, 640, 320);
    k_gather4<<<N, 80>>>(pH, pA, prowptr, pcol, pdis, b3, 320, 0, 0);

    // global mean pool
    k_pool2<<<G, 320>>>(pA, batch, ppool, N);

    // MLP head
    {
        dim3 g1(1024 / 256, G);
        k_mlp<<<g1, 256>>>(ppool, Wg1, bg1, pm1, 320, 1024, 320, 1024, 0, 1);
        dim3 g2(1, G);
        k_mlp<<<g2, 128>>>(pm1, Wg2, bg2, pmc, 1024, 128, 1024, 193, 65, 0);
        k_copyfp<<<(64 * 65 + 255) / 256, 256>>>(fp_x, pmc);
        dim3 g3(1024 / 256, G);
        k_mlp<<<g3, 256>>>(pmc, Wf1, bf1, pm3, 193, 1024, 193, 1024, 0, 1);
        dim3 g4(512 / 256, G);
        k_mlp<<<g4, 256>>>(pm3, Wf2, bf2, pm4, 1024, 512, 1024, 512, 0, 1);
        k_final<<<G, 32>>>(pm4, Wo, bo, (float*)d_out);
    }
}

// round 10
// speedup vs baseline: 1.2963x; 1.2963x over previous
#include <cuda_runtime.h>
#include <cstdint>

// ===================== scratch (device globals; no allocation allowed) ======
#define MAXN 20000
#define MAXE 400000
__device__ float g_H[(size_t)MAXN * 1280];    // GEMM out (fp32, dis[row]-scaled)
__device__ float g_X[(size_t)MAXN * 1280];    // GEMM input (tf32-rounded fp32)
__device__ float g_A[(size_t)MAXN * 320];     // layer-3 gather out (fp32)
__device__ float g_WT1[1280 * 1280];
__device__ float g_WT2[640 * 1280];
__device__ float g_WT3[320 * 640];
__device__ float g_dis[MAXN];
__device__ int   g_deg[MAXN];
__device__ int   g_rowptr[MAXN + 1];
__device__ int   g_cursor[MAXN];
__device__ int   g_col[MAXE];

// ===================== helpers =====================
__device__ __forceinline__ uint32_t f2tf32(float x) {
    uint32_t r;
    asm("cvt.rna.tf32.f32 %0, %1;" : "=r"(r) : "f"(x));
    return r;
}
__device__ __forceinline__ void mma_tf32(float* d, const uint32_t* a, const uint32_t* b) {
    asm volatile(
        "mma.sync.aligned.m16n8k8.row.col.f32.tf32.tf32.f32 "
        "{%0,%1,%2,%3}, {%4,%5,%6,%7}, {%8,%9}, {%0,%1,%2,%3};\n"
        : "+f"(d[0]), "+f"(d[1]), "+f"(d[2]), "+f"(d[3])
        : "r"(a[0]), "r"(a[1]), "r"(a[2]), "r"(a[3]), "r"(b[0]), "r"(b[1]));
}
__device__ __forceinline__ uint32_t smem_u32(const void* p) {
    uint32_t a;
    asm("{ .reg .u64 t; cvta.to.shared.u64 t, %1; cvt.u32.u64 %0, t; }" : "=r"(a) : "l"(p));
    return a;
}

// ===================== degree / normalization =====================
__global__ void k_init_deg(int* deg, int n) {
    int i = blockIdx.x * blockDim.x + threadIdx.x;
    if (i < n) deg[i] = 1;
}
__global__ void k_count_deg(const int* __restrict__ dst, int* deg, int e) {
    int i = blockIdx.x * blockDim.x + threadIdx.x;
    if (i < e) atomicAdd(&deg[dst[i]], 1);
}

// ===================== CSR build =====================
// single-block scan (warp-shuffle); also emits dis = rsqrt(deg)
#define SCHUNK 20
__global__ void __launch_bounds__(1024)
k_scan(const int* __restrict__ deg, int* __restrict__ rowptr,
       int* __restrict__ cursor, float* __restrict__ dis, int n) {
    __shared__ int warpsum[32];
    const int tid = threadIdx.x;
    const int lane = tid & 31, wid = tid >> 5;
    const int chunk = (n + 1023) / 1024;   // <= SCHUNK for n <= 20480
    const int start = tid * chunk;
    const int end = (start + chunk < n) ? start + chunk : n;
    int dcache[SCHUNK];
    int s = 0;
    for (int i = start; i < end; i++) { dcache[i - start] = deg[i]; s += dcache[i - start]; }
    int v = s;
#pragma unroll
    for (int o = 1; o < 32; o <<= 1) {
        int u = __shfl_up_sync(0xFFFFFFFFu, v, o);
        if (lane >= o) v += u;
    }
    if (lane == 31) warpsum[wid] = v;
    __syncthreads();
    if (wid == 0) {
        int w = warpsum[lane];
#pragma unroll
        for (int o = 1; o < 32; o <<= 1) {
            int u = __shfl_up_sync(0xFFFFFFFFu, w, o);
            if (lane >= o) w += u;
        }
        warpsum[lane] = w;
    }
    __syncthreads();
    int incl = v + (wid ? warpsum[wid - 1] : 0);
    int run = incl - s;                 // exclusive prefix
    for (int i = start; i < end; i++) {
        rowptr[i] = run;
        cursor[i] = run;
        dis[i] = rsqrtf((float)dcache[i - start]);
        run += dcache[i - start];
    }
    if (start < n && end == n) rowptr[n] = run;
}

// edges + self loops in one launch
__global__ void k_fill(const int* __restrict__ src, const int* __restrict__ dst,
                       int* cursor, int* __restrict__ col, int e, int n) {
    int i = blockIdx.x * blockDim.x + threadIdx.x;
    if (i < e) {
        int pos = atomicAdd(&cursor[dst[i]], 1);
        col[pos] = src[i];
    } else if (i < e + n) {
        int j = i - e;
        int pos = atomicAdd(&cursor[j], 1);
        col[pos] = j;
    }
}

// ===================== conversions =====================
__global__ void k_f2tf(const float* __restrict__ in, float* __restrict__ out, size_t n4) {
    size_t i = (size_t)blockIdx.x * blockDim.x + threadIdx.x;
    if (i < n4) {
        float4 v = *(const float4*)(in + i * 4);
        float4 o;
        o.x = __uint_as_float(f2tf32(v.x));
        o.y = __uint_as_float(f2tf32(v.y));
        o.z = __uint_as_float(f2tf32(v.z));
        o.w = __uint_as_float(f2tf32(v.w));
        *(float4*)(out + i * 4) = o;
    }
}

__global__ void k_wt(const float* __restrict__ W, float* __restrict__ WT,
                     int K, int M) {
    __shared__ float t[32][33];
    int k0 = blockIdx.y * 32, m0 = blockIdx.x * 32;
    int tx = threadIdx.x, ty = threadIdx.y;   // 32 x 8
#pragma unroll
    for (int i = ty; i < 32; i += 8)
        t[i][tx] = W[(size_t)(k0 + i) * M + m0 + tx];
    __syncthreads();
#pragma unroll
    for (int i = ty; i < 32; i += 8)
        WT[(size_t)(m0 + i) * K + k0 + tx] = __uint_as_float(f2tf32(t[tx][i]));
}

// ===================== tf32 tensor-core GEMM (cp.async, 5-stage) ============
// C[N, M] = (Atf[N, K] @ WT[M, K]^T) * dis[row]    (C fp32)
// Block tile 128x128, BK=16, 256 threads (8 warps 2x4), warp tile 64x32.
#define GW 20
#define STAGE_WORDS (128 * GW * 2)
#define NSTAGE 5

__global__ void __launch_bounds__(256, 2)
k_gemm_tf(const float* __restrict__ Atf, const float* __restrict__ WT,
          float* __restrict__ C, const float* __restrict__ dis,
          int N, int K, int M) {
    extern __shared__ uint32_t smem[];
    const uint32_t sbase0 = smem_u32(smem);
    const int tid = threadIdx.x;
    const int wid = tid >> 5;
    const int lid = tid & 31;
    const int g4  = lid >> 2;
    const int tg  = lid & 3;
    const int wm  = wid >> 2;
    const int wn  = wid & 3;
    const int row0 = blockIdx.y * 128;
    const int col0 = blockIdx.x * 128;
    const int nk = K >> 4;

    float acc[4][4][4];
#pragma unroll
    for (int i = 0; i < 4; i++)
#pragma unroll
        for (int j = 0; j < 4; j++)
#pragma unroll
            for (int k = 0; k < 4; k++) acc[i][j][k] = 0.0f;

    auto load_stage = [&](int s, int kt) {
        const int k0 = kt << 4;
        const uint32_t sb = sbase0 + (uint32_t)s * STAGE_WORDS * 4;
#pragma unroll
        for (int i = 0; i < 2; i++) {
            int c = tid + i * 256;
            int row = c >> 2, off = c & 3;
            int gr = row0 + row;
            int grc = gr < N ? gr : N - 1;
            const float* src = Atf + (size_t)grc * K + k0 + off * 4;
            uint32_t dst = sb + (uint32_t)(row * GW + off * 4) * 4;
            int sz = (gr < N) ? 16 : 0;
            asm volatile("cp.async.cg.shared.global [%0], [%1], 16, %2;"
                         :: "r"(dst), "l"(src), "r"(sz));
        }
#pragma unroll
        for (int i = 0; i < 2; i++) {
            int c = tid + i * 256;
            int n = c >> 2, off = c & 3;
            int gc = col0 + n;
            int gcc = gc < M ? gc : M - 1;
            const float* src = WT + (size_t)gcc * K + k0 + off * 4;
            uint32_t dst = sb + (uint32_t)(128 * GW + n * GW + off * 4) * 4;
            int sz = (gc < M) ? 16 : 0;
            asm volatile("cp.async.cg.shared.global [%0], [%1], 16, %2;"
                         :: "r"(dst), "l"(src), "r"(sz));
        }
        asm volatile("cp.async.commit_group;" ::: "memory");
    };

    for (int s = 0; s < NSTAGE - 1 && s < nk; s++) load_stage(s, s);

    for (int t = 0; t < nk; t++) {
        if (t + NSTAGE - 1 <= nk)
            asm volatile("cp.async.wait_group %0;" :: "n"(NSTAGE - 2) : "memory");
        else
            asm volatile("cp.async.wait_group 0;" ::: "memory");
        __syncthreads();
        if (t + NSTAGE - 1 < nk) load_stage((t + NSTAGE - 1) % NSTAGE, t + NSTAGE - 1);

        const uint32_t* as = smem + ((t % NSTAGE) * STAGE_WORDS);
        const uint32_t* bs = as + 128 * GW;
#pragma unroll
        for (int s = 0; s < 2; s++) {
            const int kw = s * 8;
            uint32_t af[4][4], bf[4][2];
#pragma unroll
            for (int mi = 0; mi < 4; mi++) {
                int r = wm * 64 + mi * 16 + g4;
                af[mi][0] = as[r * GW + kw + tg];
                af[mi][1] = as[(r + 8) * GW + kw + tg];
                af[mi][2] = as[r * GW + kw + tg + 4];
                af[mi][3] = as[(r + 8) * GW + kw + tg + 4];
            }
#pragma unroll
            for (int nf = 0; nf < 4; nf++) {
                int cc = wn * 32 + nf * 8 + g4;
                bf[nf][0] = bs[cc * GW + kw + tg];
                bf[nf][1] = bs[cc * GW + kw + tg + 4];
            }
#pragma unroll
            for (int mi = 0; mi < 4; mi++)
#pragma unroll
                for (int nf = 0; nf < 4; nf++)
                    mma_tf32(acc[mi][nf], af[mi], bf[nf]);
        }
    }

#pragma unroll
    for (int mi = 0; mi < 4; mi++) {
        int r0 = row0 + wm * 64 + mi * 16 + g4;
        float d0 = (r0 < N) ? dis[r0] : 0.f;
        float d1 = (r0 + 8 < N) ? dis[r0 + 8] : 0.f;
#pragma unroll
        for (int nf = 0; nf < 4; nf++) {
            int cc = col0 + wn * 32 + nf * 8 + tg * 2;
            if (cc < M) {
                if (r0 < N)
                    *(float2*)(C + (size_t)r0 * M + cc) =
                        make_float2(acc[mi][nf][0] * d0, acc[mi][nf][1] * d0);
                if (r0 + 8 < N)
                    *(float2*)(C + (size_t)(r0 + 8) * M + cc) =
                        make_float2(acc[mi][nf][2] * d1, acc[mi][nf][3] * d1);
            }
        }
    }
}

// ===================== CSR gather (float4, edge-unrolled) ====================
__global__ void k_gather4(const float* __restrict__ H, float* __restrict__ out,
                          const int* __restrict__ rowptr, const int* __restrict__ col,
                          const float* __restrict__ dis, const float* __restrict__ b,
                          int M, int fo, int tfround) {
    const int d = blockIdx.x;
    const int t = threadIdx.x;
    float4 acc = make_float4(0.f, 0.f, 0.f, 0.f);
    const int beg = rowptr[d];
    const int end = rowptr[d + 1];
    int j = beg;
    for (; j + 1 < end; j += 2) {
        const int s0 = __ldg(&col[j]);
        const int s1 = __ldg(&col[j + 1]);
        float4 v0 = __ldg((const float4*)(H + (size_t)s0 * M + fo) + t);
        float4 v1 = __ldg((const float4*)(H + (size_t)s1 * M + fo) + t);
        acc.x += v0.x + v1.x;
        acc.y += v0.y + v1.y;
        acc.z += v0.z + v1.z;
        acc.w += v0.w + v1.w;
    }
    if (j < end) {
        const int s0 = __ldg(&col[j]);
        float4 v0 = __ldg((const float4*)(H + (size_t)s0 * M + fo) + t);
        acc.x += v0.x; acc.y += v0.y; acc.z += v0.z; acc.w += v0.w;
    }
    const float wd = dis[d];
    float4 bb = __ldg((const float4*)(b + fo) + t);
    float4 r;
    r.x = fmaxf(acc.x * wd + bb.x, 0.f);
    r.y = fmaxf(acc.y * wd + bb.y, 0.f);
    r.z = fmaxf(acc.z * wd + bb.z, 0.f);
    r.w = fmaxf(acc.w * wd + bb.w, 0.f);
    if (tfround) {
        r.x = __uint_as_float(f2tf32(r.x));
        r.y = __uint_as_float(f2tf32(r.y));
        r.z = __uint_as_float(f2tf32(r.z));
        r.w = __uint_as_float(f2tf32(r.w));
    }
    ((float4*)(out + (size_t)d * M + fo))[t] = r;
}

// ===================== fused mean-pool + MLP head ===========================
// grid = G blocks, 512 threads. All intermediates staged in SMEM.
__global__ void __launch_bounds__(512)
k_head(const float* __restrict__ A, const int* __restrict__ batch,
       const float* __restrict__ fp_x,
       const float* __restrict__ Wg1, const float* __restrict__ bg1,
       const float* __restrict__ Wg2, const float* __restrict__ bg2,
       const float* __restrict__ Wf1, const float* __restrict__ bf1,
       const float* __restrict__ Wf2, const float* __restrict__ bf2,
       const float* __restrict__ Wo, const float* __restrict__ bo,
       float* __restrict__ out, int N) {
    __shared__ float xt[320];
    __shared__ float mc[193];
    __shared__ float m1[1024];
    __shared__ float m3[1024];
    __shared__ float m4[512];
    __shared__ float p2[4][128];
    __shared__ float red[16];
    const int g = blockIdx.x;
    const int tid = threadIdx.x;

    // mean pool (batch is sorted: binary search graph bounds)
    int lo = 0, hi = N;
    while (lo < hi) { int mid = (lo + hi) >> 1; if (batch[mid] < g) lo = mid + 1; else hi = mid; }
    const int beg = lo;
    hi = N;
    while (lo < hi) { int mid = (lo + hi) >> 1; if (batch[mid] < g + 1) lo = mid + 1; else hi = mid; }
    const int end = lo;
    if (tid < 320) {
        float s = 0.f;
        for (int i = beg; i < end; i++) s += A[(size_t)i * 320 + tid];
        xt[tid] = s / fmaxf((float)(end - beg), 1.0f);
    }
    __syncthreads();

    // m1 = relu(xt @ Wg1 + bg1)   [1024]
    for (int m = tid; m < 1024; m += 512) {
        float acc = bg1[m];
        for (int k = 0; k < 320; k++) acc += xt[k] * Wg1[(size_t)k * 1024 + m];
        m1[m] = fmaxf(acc, 0.f);
    }
    __syncthreads();

    // mc[65:193] = m1 @ Wg2 + bg2 (k-split over 4 thread groups); mc[0:65] = fp_x[g]
    {
        int m = tid & 127, q = tid >> 7;
        float acc = 0.f;
        for (int k = q * 256; k < (q + 1) * 256; k++) acc += m1[k] * Wg2[(size_t)k * 128 + m];
        p2[q][m] = acc;
    }
    __syncthreads();
    if (tid < 128) mc[65 + tid] = bg2[tid] + p2[0][tid] + p2[1][tid] + p2[2][tid] + p2[3][tid];
    else if (tid < 128 + 65) mc[tid - 128] = fp_x[g * 65 + (tid - 128)];
    __syncthreads();

    // m3 = relu(mc @ Wf1 + bf1)   [1024]
    for (int m = tid; m < 1024; m += 512) {
        float acc = bf1[m];
        for (int k = 0; k < 193; k++) acc += mc[k] * Wf1[(size_t)k * 1024 + m];
        m3[m] = fmaxf(acc, 0.f);
    }
    __syncthreads();

    // m4 = relu(m3 @ Wf2 + bf2)   [512]
    {
        float acc = bf2[tid];
        for (int k = 0; k < 1024; k++) acc += m3[k] * Wf2[(size_t)k * 512 + tid];
        m4[tid] = fmaxf(acc, 0.f);
    }
    __syncthreads();

    // out[g] = m4 @ Wo + bo  (block reduce)
    float acc = m4[tid] * Wo[tid];
#pragma unroll
    for (int o = 16; o; o >>= 1) acc += __shfl_down_sync(0xFFFFFFFFu, acc, o);
    if ((tid & 31) == 0) red[tid >> 5] = acc;
    __syncthreads();
    if (tid < 16) {
        float v = red[tid];
#pragma unroll
        for (int o = 8; o; o >>= 1) v += __shfl_down_sync(0xFFFFu, v, o);
        if (tid == 0) out[g] = v + bo[0];
    }
}

// ===================== launch =====================
extern "C" void kernel_launch(void* const* d_in, const int* in_sizes, int n_in,
                              void* d_out, int out_size) {
    const float* x     = (const float*)d_in[0];
    const int*   ei    = (const int*)d_in[1];
    const int*   batch = (const int*)d_in[2];
    const float* fp_x  = (const float*)d_in[3];
    const float* W1 = (const float*)d_in[4];   const float* b1 = (const float*)d_in[5];
    const float* W2 = (const float*)d_in[6];   const float* b2 = (const float*)d_in[7];
    const float* W3 = (const float*)d_in[8];   const float* b3 = (const float*)d_in[9];
    const float* Wg1 = (const float*)d_in[10]; const float* bg1 = (const float*)d_in[11];
    const float* Wg2 = (const float*)d_in[12]; const float* bg2 = (const float*)d_in[13];
    const float* Wf1 = (const float*)d_in[14]; const float* bf1 = (const float*)d_in[15];
    const float* Wf2 = (const float*)d_in[16]; const float* bf2 = (const float*)d_in[17];
    const float* Wo  = (const float*)d_in[18]; const float* bo  = (const float*)d_in[19];

    const int N = in_sizes[0] / 1280;
    const int E = in_sizes[1] / 2;
    const int G = in_sizes[3] / 65;
    const int* srcp = ei;
    const int* dstp = ei + E;

    float *pH, *pX, *pA, *pdis;
    float *pWT1, *pWT2, *pWT3;
    int *pdeg, *prowptr, *pcursor, *pcol;
    cudaGetSymbolAddress((void**)&pH, g_H);
    cudaGetSymbolAddress((void**)&pX, g_X);
    cudaGetSymbolAddress((void**)&pA, g_A);
    cudaGetSymbolAddress((void**)&pWT1, g_WT1);
    cudaGetSymbolAddress((void**)&pWT2, g_WT2);
    cudaGetSymbolAddress((void**)&pWT3, g_WT3);
    cudaGetSymbolAddress((void**)&pdis, g_dis);
    cudaGetSymbolAddress((void**)&pdeg, g_deg);
    cudaGetSymbolAddress((void**)&prowptr, g_rowptr);
    cudaGetSymbolAddress((void**)&pcursor, g_cursor);
    cudaGetSymbolAddress((void**)&pcol, g_col);

    cudaFuncSetAttribute(k_gemm_tf, cudaFuncAttributeMaxDynamicSharedMemorySize,
                         NSTAGE * STAGE_WORDS * 4);

    // degree / normalization / CSR
    k_init_deg<<<(N + 255) / 256, 256>>>(pdeg, N);
    k_count_deg<<<(E + 255) / 256, 256>>>(dstp, pdeg, E);
    k_scan<<<1, 1024>>>(pdeg, prowptr, pcursor, pdis, N);
    k_fill<<<(E + N + 255) / 256, 256>>>(srcp, dstp, pcursor, pcol, E, N);

    // conversions: x -> tf32-rounded fp32, weights -> tf32 transposed
    {
        size_t n4 = (size_t)N * 1280 / 4;
        k_f2tf<<<(unsigned)((n4 + 255) / 256), 256>>>(x, pX, n4);
        dim3 bt(32, 8);
        k_wt<<<dim3(1280 / 32, 1280 / 32), bt>>>(W1, pWT1, 1280, 1280);
        k_wt<<<dim3(640 / 32, 1280 / 32), bt>>>(W2, pWT2, 1280, 640);
        k_wt<<<dim3(320 / 32, 640 / 32), bt>>>(W3, pWT3, 640, 320);
    }

    const unsigned smem_bytes = NSTAGE * STAGE_WORDS * 4;
    auto gemm = [&](const float* in, const float* WT, int K, int M) {
        dim3 gg((M + 127) / 128, (N + 127) / 128);
        k_gemm_tf<<<gg, 256, smem_bytes>>>(in, WT, pH, pdis, N, K, M);
    };

    // layer 1 (gather in two 640-feature passes to keep H-half L2-resident)
    gemm(pX, pWT1, 1280, 1280);
    k_gather4<<<N, 160>>>(pH, pX, prowptr, pcol, pdis, b1, 1280, 0,   1);
    k_gather4<<<N, 160>>>(pH, pX, prowptr, pcol, pdis, b1, 1280, 640, 1);
    // layer 2
    gemm(pX, pWT2, 1280, 640);
    k_gather4<<<N, 160>>>(pH, pX, prowptr, pcol, pdis, b2, 640, 0, 1);
    // layer 3
    gemm(pX, pWT3, 640, 320);
    k_gather4<<<N, 80>>>(pH, pA, prowptr, pcol, pdis, b3, 320, 0, 0);

    // fused mean-pool + MLP head
    k_head<<<G, 512>>>(pA, batch, fp_x, Wg1, bg1, Wg2, bg2,
                       Wf1, bf1, Wf2, bf2, Wo, bo, (float*)d_out, N);
}